// round 1
// baseline (speedup 1.0000x reference)
#include <cuda_runtime.h>
#include <math.h>

// Problem constants
static constexpr int B_  = 2;
static constexpr int S_  = 2048;
static constexpr int D_  = 512;
static constexpr int H_  = 8;
static constexpr int DK_ = 64;
static constexpr int DF_ = 2048;
static constexpr int M_  = B_ * S_;          // 4096 rows total
static constexpr long long QKV_ELEMS = (long long)B_ * H_ * S_ * DK_;   // 2,097,152
static constexpr long long SC_ELEMS  = (long long)B_ * H_ * S_ * S_;    // 67,108,864

// -------- scratch (device globals; no allocation allowed in kernel_launch) --------
__device__ float g_q[QKV_ELEMS];
__device__ float g_k[QKV_ELEMS];
__device__ float g_v[QKV_ELEMS];
__device__ float g_scores[SC_ELEMS];
__device__ float g_ocat[(long long)M_ * D_];
__device__ float g_h1[(long long)M_ * D_];
__device__ float g_h [(long long)M_ * D_];
__device__ float g_ff[(long long)M_ * DF_];
__device__ float g_h2[(long long)M_ * D_];

// -------- batched offset descriptor: off(z) = (z/div)*s1 + (z%div)*s2 --------
struct Off { int div; long long s1; long long s2; };
__device__ __forceinline__ long long offz(Off o, int z) {
    return (long long)(z / o.div) * o.s1 + (long long)(z % o.div) * o.s2;
}

// =====================================================================
// Generic tiled fp32 GEMM.
//   C[z] = alpha * A[z] @ (TB ? B[z]^T : B[z]) (+bias) (+relu | +residual)
// EPI: 0 = bias only, 1 = bias+relu, 2 = bias+residual (res indexed m*ldc+n,
//      only used with gridDim.z == 1)
// A is row-major [M,K]; B is [K,N] (TB=false) or [N,K] (TB=true).
// All tile dims divide exactly for every launch below (no bounds checks).
// =====================================================================
template<int BM, int BN, int BK, int TM, int TN, bool TB, int EPI>
__global__ void __launch_bounds__((BM / TM) * (BN / TN))
gemm_k(const float* __restrict__ A, const float* __restrict__ Bp,
       const float* __restrict__ bias, const float* __restrict__ res,
       float* __restrict__ C,
       int M, int N, int K, int ldc, float alpha,
       Off oA, Off oB, Off oBias, Off oC)
{
    constexpr int NT = (BM / TM) * (BN / TN);   // threads per block
    constexpr int TX = BN / TN;
    constexpr int KV = BK / 4;                  // float4 per A-tile row
    constexpr int A_IT = (BM * BK / 4) / NT;
    constexpr int B_IT = (BK * BN / 4) / NT;
    constexpr int B_ROWV = BN / 4;

    const int tid = threadIdx.x;
    const int z = blockIdx.z;

    A  += offz(oA, z);
    Bp += offz(oB, z);
    C  += offz(oC, z);
    const bool has_bias = (bias != nullptr);
    if (has_bias) bias += offz(oBias, z);

    const int bm = blockIdx.y * BM;
    const int bn = blockIdx.x * BN;

    __shared__ float As[BK][BM];
    __shared__ float Bs[BK][BN + 4];

    const int tx = tid % TX;
    const int ty = tid / TX;

    float acc[TM][TN];
#pragma unroll
    for (int i = 0; i < TM; i++)
#pragma unroll
        for (int j = 0; j < TN; j++) acc[i][j] = 0.0f;

    for (int k0 = 0; k0 < K; k0 += BK) {
        // ---- stage A tile (transposed into smem) ----
#pragma unroll
        for (int i = 0; i < A_IT; i++) {
            int e = tid + i * NT;
            int r = e / KV, cv = e % KV;
            float4 v = *reinterpret_cast<const float4*>(
                A + (long long)(bm + r) * K + k0 + cv * 4);
            As[cv * 4 + 0][r] = v.x;
            As[cv * 4 + 1][r] = v.y;
            As[cv * 4 + 2][r] = v.z;
            As[cv * 4 + 3][r] = v.w;
        }
        // ---- stage B tile ----
        if (!TB) {
#pragma unroll
            for (int i = 0; i < B_IT; i++) {
                int e = tid + i * NT;
                int r = e / B_ROWV, cv = e % B_ROWV;
                float4 v = *reinterpret_cast<const float4*>(
                    Bp + (long long)(k0 + r) * N + bn + cv * 4);
                *reinterpret_cast<float4*>(&Bs[r][cv * 4]) = v;
            }
        } else {
#pragma unroll
            for (int i = 0; i < B_IT; i++) {
                int e = tid + i * NT;
                int r = e / KV, cv = e % KV;   // r = n within tile
                float4 v = *reinterpret_cast<const float4*>(
                    Bp + (long long)(bn + r) * K + k0 + cv * 4);
                Bs[cv * 4 + 0][r] = v.x;
                Bs[cv * 4 + 1][r] = v.y;
                Bs[cv * 4 + 2][r] = v.z;
                Bs[cv * 4 + 3][r] = v.w;
            }
        }
        __syncthreads();

        // ---- register-tiled FMA ----
#pragma unroll
        for (int kk = 0; kk < BK; kk++) {
            float a[TM], b[TN];
#pragma unroll
            for (int i = 0; i < TM; i += 4)
                *reinterpret_cast<float4*>(&a[i]) =
                    *reinterpret_cast<const float4*>(&As[kk][ty * TM + i]);
#pragma unroll
            for (int j = 0; j < TN; j += 4)
                *reinterpret_cast<float4*>(&b[j]) =
                    *reinterpret_cast<const float4*>(&Bs[kk][tx * TN + j]);
#pragma unroll
            for (int i = 0; i < TM; i++)
#pragma unroll
                for (int j = 0; j < TN; j++)
                    acc[i][j] = fmaf(a[i], b[j], acc[i][j]);
        }
        __syncthreads();
    }

    // ---- epilogue ----
#pragma unroll
    for (int i = 0; i < TM; i++) {
        int m = bm + ty * TM + i;
#pragma unroll
        for (int j = 0; j < TN; j++) {
            int n = bn + tx * TN + j;
            float v = acc[i][j] * alpha;
            if (has_bias) v += bias[n];
            if (EPI == 1) v = v > 0.0f ? v : 0.0f;
            if (EPI == 2) v += res[(long long)m * ldc + n];
            C[(long long)m * ldc + n] = v;
        }
    }
}

// =====================================================================
// Row softmax in place. One block (256 threads) per row of 2048 floats.
// =====================================================================
__global__ void __launch_bounds__(256) softmax_rows_k(float* __restrict__ P)
{
    float4* r = reinterpret_cast<float4*>(P + (long long)blockIdx.x * S_);
    const int tid = threadIdx.x;

    float4 v0 = r[tid];
    float4 v1 = r[tid + 256];

    float mx = fmaxf(fmaxf(fmaxf(v0.x, v0.y), fmaxf(v0.z, v0.w)),
                     fmaxf(fmaxf(v1.x, v1.y), fmaxf(v1.z, v1.w)));
#pragma unroll
    for (int o = 16; o; o >>= 1) mx = fmaxf(mx, __shfl_xor_sync(0xffffffffu, mx, o));

    __shared__ float sred[8];
    if ((tid & 31) == 0) sred[tid >> 5] = mx;
    __syncthreads();
    float rowmax = sred[0];
#pragma unroll
    for (int w = 1; w < 8; w++) rowmax = fmaxf(rowmax, sred[w]);
    __syncthreads();

    v0.x = __expf(v0.x - rowmax); v0.y = __expf(v0.y - rowmax);
    v0.z = __expf(v0.z - rowmax); v0.w = __expf(v0.w - rowmax);
    v1.x = __expf(v1.x - rowmax); v1.y = __expf(v1.y - rowmax);
    v1.z = __expf(v1.z - rowmax); v1.w = __expf(v1.w - rowmax);

    float s = v0.x + v0.y + v0.z + v0.w + v1.x + v1.y + v1.z + v1.w;
#pragma unroll
    for (int o = 16; o; o >>= 1) s += __shfl_xor_sync(0xffffffffu, s, o);
    if ((tid & 31) == 0) sred[tid >> 5] = s;
    __syncthreads();
    float tot = 0.0f;
#pragma unroll
    for (int w = 0; w < 8; w++) tot += sred[w];
    float inv = __frcp_rn(tot);

    v0.x *= inv; v0.y *= inv; v0.z *= inv; v0.w *= inv;
    v1.x *= inv; v1.y *= inv; v1.z *= inv; v1.w *= inv;
    r[tid] = v0;
    r[tid + 256] = v1;
}

// =====================================================================
// Row LayerNorm: out = (x - mu) * rsqrt(var + eps) * g + b.
// One block (128 threads) per row of 512 floats; float4 per thread.
// =====================================================================
__global__ void __launch_bounds__(128)
layernorm_k(const float* __restrict__ in, const float* __restrict__ g,
            const float* __restrict__ b, float* __restrict__ out)
{
    const int tid = threadIdx.x;
    const float4* r = reinterpret_cast<const float4*>(in + (long long)blockIdx.x * D_);
    float4 v = r[tid];

    float s  = v.x + v.y + v.z + v.w;
    float sq = v.x * v.x + v.y * v.y + v.z * v.z + v.w * v.w;
#pragma unroll
    for (int o = 16; o; o >>= 1) {
        s  += __shfl_xor_sync(0xffffffffu, s, o);
        sq += __shfl_xor_sync(0xffffffffu, sq, o);
    }
    __shared__ float ssum[4], ssq[4];
    if ((tid & 31) == 0) { ssum[tid >> 5] = s; ssq[tid >> 5] = sq; }
    __syncthreads();
    s  = ssum[0] + ssum[1] + ssum[2] + ssum[3];
    sq = ssq[0] + ssq[1] + ssq[2] + ssq[3];

    const float mu  = s * (1.0f / D_);
    float var = sq * (1.0f / D_) - mu * mu;
    var = fmaxf(var, 0.0f);
    const float rstd = rsqrtf(var + 1e-5f);

    float4 gg = reinterpret_cast<const float4*>(g)[tid];
    float4 bb = reinterpret_cast<const float4*>(b)[tid];
    float4 o4;
    o4.x = (v.x - mu) * rstd * gg.x + bb.x;
    o4.y = (v.y - mu) * rstd * gg.y + bb.y;
    o4.z = (v.z - mu) * rstd * gg.z + bb.z;
    o4.w = (v.w - mu) * rstd * gg.w + bb.w;
    reinterpret_cast<float4*>(out + (long long)blockIdx.x * D_)[tid] = o4;
}

// =====================================================================
// Launcher
// =====================================================================
extern "C" void kernel_launch(void* const* d_in, const int* in_sizes, int n_in,
                              void* d_out, int out_size)
{
    (void)in_sizes; (void)n_in; (void)out_size;
    const float* x     = (const float*)d_in[0];
    const float* Wq    = (const float*)d_in[1];
    const float* bq    = (const float*)d_in[2];
    const float* Wk    = (const float*)d_in[3];
    const float* bk    = (const float*)d_in[4];
    const float* Wv    = (const float*)d_in[5];
    const float* bv    = (const float*)d_in[6];
    const float* Wo    = (const float*)d_in[7];
    const float* bo    = (const float*)d_in[8];
    const float* ln1_g = (const float*)d_in[9];
    const float* ln1_b = (const float*)d_in[10];
    const float* W1    = (const float*)d_in[11];
    const float* b1    = (const float*)d_in[12];
    const float* W2    = (const float*)d_in[13];
    const float* b2    = (const float*)d_in[14];
    const float* ln2_g = (const float*)d_in[15];
    const float* ln2_b = (const float*)d_in[16];
    float* out = (float*)d_out;

    float *q, *k, *v, *sc, *oc, *h1, *h, *ff, *h2;
    cudaGetSymbolAddress((void**)&q,  g_q);
    cudaGetSymbolAddress((void**)&k,  g_k);
    cudaGetSymbolAddress((void**)&v,  g_v);
    cudaGetSymbolAddress((void**)&sc, g_scores);
    cudaGetSymbolAddress((void**)&oc, g_ocat);
    cudaGetSymbolAddress((void**)&h1, g_h1);
    cudaGetSymbolAddress((void**)&h,  g_h);
    cudaGetSymbolAddress((void**)&ff, g_ff);
    cudaGetSymbolAddress((void**)&h2, g_h2);

    const Off lin0   = {1, 0, 0};
    const Off oA_qkv = {H_, (long long)S_ * D_, 0};           // A = x[b]
    const Off oB_qkv = {H_, 0, (long long)D_ * DK_};          // B = W[h]
    const Off oBias_qkv = {H_, 0, (long long)DK_};            // bias[h]
    const Off oC_qkv = {1, (long long)S_ * DK_, 0};           // C = buf[z]
    const Off oBH    = {1, (long long)S_ * DK_, 0};
    const Off oSC    = {1, (long long)S_ * S_, 0};
    const Off oCat   = {H_, (long long)S_ * D_, (long long)DK_}; // b*S*D + h*DK

    // ---- 1-3. per-head QKV projections:  [2048,512] @ [512,64] + bias, z = b*H+h ----
    gemm_k<128, 64, 16, 8, 4, false, 0><<<dim3(1, 16, B_ * H_), 256>>>(
        x, Wq, bq, nullptr, q, S_, DK_, D_, DK_, 1.0f, oA_qkv, oB_qkv, oBias_qkv, oC_qkv);
    gemm_k<128, 64, 16, 8, 4, false, 0><<<dim3(1, 16, B_ * H_), 256>>>(
        x, Wk, bk, nullptr, k, S_, DK_, D_, DK_, 1.0f, oA_qkv, oB_qkv, oBias_qkv, oC_qkv);
    gemm_k<128, 64, 16, 8, 4, false, 0><<<dim3(1, 16, B_ * H_), 256>>>(
        x, Wv, bv, nullptr, v, S_, DK_, D_, DK_, 1.0f, oA_qkv, oB_qkv, oBias_qkv, oC_qkv);

    // ---- 4. scores = (q @ k^T) / sqrt(DK), per (b,h):  [2048,64] @ [2048,64]^T ----
    gemm_k<128, 128, 16, 8, 8, true, 0><<<dim3(16, 16, B_ * H_), 256>>>(
        q, k, nullptr, nullptr, sc, S_, S_, DK_, S_, 0.125f, oBH, oBH, lin0, oSC);

    // ---- 5. softmax over rows ----
    softmax_rows_k<<<B_ * H_ * S_, 256>>>(sc);

    // ---- 6. o = attn @ v, written straight into concat layout [4096,512] ----
    gemm_k<128, 64, 16, 8, 4, false, 0><<<dim3(1, 16, B_ * H_), 256>>>(
        sc, v, nullptr, nullptr, oc, S_, DK_, S_, D_, 1.0f, oSC, oBH, lin0, oCat);

    // ---- 7. h1 = x + ocat @ Wo + bo ----
    gemm_k<128, 64, 16, 8, 4, false, 2><<<dim3(8, 32, 1), 256>>>(
        oc, Wo, bo, x, h1, M_, D_, D_, D_, 1.0f, lin0, lin0, lin0, lin0);

    // ---- 8. h = LN1(h1) ----
    layernorm_k<<<M_, 128>>>(h1, ln1_g, ln1_b, h);

    // ---- 9. ff = relu(h @ W1 + b1) ----
    gemm_k<128, 128, 16, 8, 8, false, 1><<<dim3(16, 32, 1), 256>>>(
        h, W1, b1, nullptr, ff, M_, DF_, D_, DF_, 1.0f, lin0, lin0, lin0, lin0);

    // ---- 10. h2 = h + ff @ W2 + b2 ----
    gemm_k<128, 64, 16, 8, 4, false, 2><<<dim3(8, 32, 1), 256>>>(
        ff, W2, b2, h, h2, M_, D_, DF_, D_, 1.0f, lin0, lin0, lin0, lin0);

    // ---- 11. out = LN2(h2) ----
    layernorm_k<<<M_, 128>>>(h2, ln2_g, ln2_b, out);
}

// round 4
// speedup vs baseline: 2.8509x; 2.8509x over previous
#include <cuda_runtime.h>
#include <cstdint>
#include <math.h>

// Problem constants
static constexpr int B_  = 2;
static constexpr int S_  = 2048;
static constexpr int D_  = 512;
static constexpr int H_  = 8;
static constexpr int DK_ = 64;
static constexpr int DF_ = 2048;
static constexpr int M_  = B_ * S_;
static constexpr long long QKV_ELEMS = (long long)B_ * H_ * S_ * DK_;
static constexpr long long SC_ELEMS  = (long long)B_ * H_ * S_ * S_;

// -------- scratch (device globals; no allocation allowed) --------
__device__ float g_q[QKV_ELEMS];
__device__ float g_k[QKV_ELEMS];
__device__ float g_v[QKV_ELEMS];
__device__ float g_vT[QKV_ELEMS];                 // [z][64][2048]
__device__ float g_scores[SC_ELEMS];
__device__ float g_ocat[(long long)M_ * D_];
__device__ float g_h1[(long long)M_ * D_];
__device__ float g_h [(long long)M_ * D_];
__device__ float g_ff[(long long)M_ * DF_];
__device__ float g_h2[(long long)M_ * D_];
__device__ float g_WqT[(long long)H_ * DK_ * D_]; // [h][64][512]
__device__ float g_WkT[(long long)H_ * DK_ * D_];
__device__ float g_WvT[(long long)H_ * DK_ * D_];
__device__ float g_WoT[(long long)D_ * D_];
__device__ float g_W1T[(long long)DF_ * D_];
__device__ float g_W2T[(long long)D_ * DF_];

// -------- batched offset descriptor --------
struct Off { int div; long long s1; long long s2; };
__device__ __forceinline__ long long offz(Off o, int z) {
    return (long long)(z / o.div) * o.s1 + (long long)(z % o.div) * o.s2;
}

// ===================== PTX helpers (baseline sm_80+ features only) =====================
__device__ __forceinline__ uint32_t smem_u32(const void* p) {
    uint32_t a;
    asm("{ .reg .u64 t; cvta.to.shared.u64 t, %1; cvt.u32.u64 %0, t; }" : "=r"(a) : "l"(p));
    return a;
}
__device__ __forceinline__ void cp16(uint32_t dst, const float* src) {
    asm volatile("cp.async.cg.shared.global [%0], [%1], 16;"
                 :: "r"(dst), "l"(__cvta_generic_to_global(src)) : "memory");
}
__device__ __forceinline__ uint32_t f2tf(float f) {
    uint32_t u;
    asm("cvt.rna.tf32.f32 %0, %1;" : "=r"(u) : "f"(f));
    return u;
}
__device__ __forceinline__ void mma8(float* d, const uint32_t* a, const uint32_t* b) {
    asm volatile(
        "mma.sync.aligned.m16n8k8.row.col.f32.tf32.tf32.f32 "
        "{%0,%1,%2,%3}, {%4,%5,%6,%7}, {%8,%9}, {%0,%1,%2,%3};"
        : "+f"(d[0]), "+f"(d[1]), "+f"(d[2]), "+f"(d[3])
        : "r"(a[0]), "r"(a[1]), "r"(a[2]), "r"(a[3]), "r"(b[0]), "r"(b[1]));
}

// =====================================================================
// tf32 mma.sync GEMM.  C[z] = alpha * A[z] @ B[z]^T (+bias)(+relu|+res)
// A row-major [M,K]; B row-major [N,K] (K-major both sides).
// BM=128, BK=32, BN template (64/128). Warp grid 2 x (BN/32); each warp
// computes a 64x32 tile = 4x4 m16n8k8 mma tiles. cp.async double buffer.
// EPI: 0 bias, 1 bias+relu, 2 bias+residual
// =====================================================================
template<int BN, int EPI>
__global__ void __launch_bounds__(2 * (BN / 32) * 32, 2)
mma_gemm(const float* __restrict__ A, const float* __restrict__ Bm,
         const float* __restrict__ bias, const float* __restrict__ res,
         float* __restrict__ C, int M, int N, int K, int ldc, float alpha,
         Off oA, Off oB, Off oBias, Off oC)
{
    constexpr int BM = 128;
    constexpr int BK = 32;
    constexpr int AW = 36;                         // padded row stride (floats)
    constexpr int NWN = BN / 32;                   // warps along n
    constexpr int NT  = 2 * NWN * 32;              // threads (128 or 256)
    constexpr int A_FLOATS = BM * AW;
    constexpr int B_FLOATS = BN * AW;
    constexpr int A_ITERS = (BM * 8) / NT;         // 16B chunks per thread for A
    constexpr int B_ITERS = (BN * 8) / NT;

    extern __shared__ float smf[];
    float* sA = smf;                                // [2][BM][AW]
    float* sB = smf + 2 * A_FLOATS;                 // [2][BN][AW]
    const uint32_t uA = smem_u32(sA);
    const uint32_t uB = smem_u32(sB);

    const int tid  = threadIdx.x;
    const int wid  = tid >> 5;
    const int lane = tid & 31;
    const int gid  = lane >> 2;     // 0..7
    const int tig  = lane & 3;      // 0..3
    const int wn   = wid % NWN;
    const int wm   = wid / NWN;
    const int z    = blockIdx.z;

    A  += offz(oA, z);
    Bm += offz(oB, z);
    C  += offz(oC, z);
    const float* bptr = (bias != nullptr) ? bias + offz(oBias, z) : nullptr;

    const long long bm = (long long)blockIdx.y * BM;
    const long long bn = (long long)blockIdx.x * BN;
    const int T = K / BK;

    const float* aBase = A + bm * K;
    const float* bBase = Bm + bn * K;

    auto stage = [&](int t) {
        const int buf = t & 1;
        const float* aSrc = aBase + (long long)t * BK;
        const float* bSrc = bBase + (long long)t * BK;
        const uint32_t aDst = uA + (uint32_t)buf * A_FLOATS * 4;
        const uint32_t bDst = uB + (uint32_t)buf * B_FLOATS * 4;
#pragma unroll
        for (int i = 0; i < A_ITERS; i++) {
            int e = tid + i * NT;
            int r = e >> 3, c = e & 7;
            cp16(aDst + (uint32_t)(r * AW + c * 4) * 4, aSrc + (long long)r * K + c * 4);
        }
#pragma unroll
        for (int i = 0; i < B_ITERS; i++) {
            int e = tid + i * NT;
            int r = e >> 3, c = e & 7;
            cp16(bDst + (uint32_t)(r * AW + c * 4) * 4, bSrc + (long long)r * K + c * 4);
        }
        asm volatile("cp.async.commit_group;" ::: "memory");
    };

    float acc[4][4][4];
#pragma unroll
    for (int i = 0; i < 4; i++)
#pragma unroll
        for (int j = 0; j < 4; j++)
#pragma unroll
            for (int r = 0; r < 4; r++) acc[i][j][r] = 0.0f;

    stage(0);
    for (int t = 0; t < T; t++) {
        if (t + 1 < T) {
            stage(t + 1);
            asm volatile("cp.async.wait_group 1;" ::: "memory");
        } else {
            asm volatile("cp.async.wait_group 0;" ::: "memory");
        }
        __syncthreads();

        const float* As = sA + (t & 1) * A_FLOATS;
        const float* Bs = sB + (t & 1) * B_FLOATS;
#pragma unroll
        for (int ks = 0; ks < BK / 8; ks++) {
            const int kk = ks * 8 + tig;
            uint32_t af[4][4];
#pragma unroll
            for (int mi = 0; mi < 4; mi++) {
                const float* ap = As + (wm * 64 + mi * 16 + gid) * AW + kk;
                af[mi][0] = f2tf(ap[0]);
                af[mi][1] = f2tf(ap[8 * AW]);
                af[mi][2] = f2tf(ap[4]);
                af[mi][3] = f2tf(ap[8 * AW + 4]);
            }
            uint32_t bf[4][2];
#pragma unroll
            for (int nj = 0; nj < 4; nj++) {
                // B fragment: b0 = B[k = ks*8 + tig][n = gid], b1 = +4 in k
                const float* bp = Bs + (wn * 32 + nj * 8 + gid) * AW + kk;
                bf[nj][0] = f2tf(bp[0]);
                bf[nj][1] = f2tf(bp[4]);
            }
#pragma unroll
            for (int mi = 0; mi < 4; mi++)
#pragma unroll
                for (int nj = 0; nj < 4; nj++)
                    mma8(acc[mi][nj], af[mi], bf[nj]);
        }
        __syncthreads();
    }

    // ---- epilogue ----
#pragma unroll
    for (int mi = 0; mi < 4; mi++) {
        const long long m0 = bm + wm * 64 + mi * 16 + gid;
#pragma unroll
        for (int nj = 0; nj < 4; nj++) {
            const long long n0 = bn + wn * 32 + nj * 8 + tig * 2;
            float2 bb = make_float2(0.0f, 0.0f);
            if (bptr) bb = *reinterpret_cast<const float2*>(bptr + n0);

            float2 o0, o1;
            o0.x = acc[mi][nj][0] * alpha + bb.x;
            o0.y = acc[mi][nj][1] * alpha + bb.y;
            o1.x = acc[mi][nj][2] * alpha + bb.x;
            o1.y = acc[mi][nj][3] * alpha + bb.y;
            if (EPI == 1) {
                o0.x = fmaxf(o0.x, 0.0f); o0.y = fmaxf(o0.y, 0.0f);
                o1.x = fmaxf(o1.x, 0.0f); o1.y = fmaxf(o1.y, 0.0f);
            }
            if (EPI == 2) {
                float2 r0 = *reinterpret_cast<const float2*>(res + m0 * ldc + n0);
                float2 r1 = *reinterpret_cast<const float2*>(res + (m0 + 8) * ldc + n0);
                o0.x += r0.x; o0.y += r0.y;
                o1.x += r1.x; o1.y += r1.y;
            }
            *reinterpret_cast<float2*>(C + m0 * ldc + n0) = o0;
            *reinterpret_cast<float2*>(C + (m0 + 8) * ldc + n0) = o1;
        }
    }
}

// =====================================================================
// 32x32 tiled transpose: out[z][c][r] = in[z][r][c]
// =====================================================================
__global__ void __launch_bounds__(256)
transpose_k(const float* __restrict__ in, float* __restrict__ out,
            int R, int Cc, long long zin, long long zout)
{
    __shared__ float t[32][33];
    const float* ip = in + (long long)blockIdx.z * zin;
    float* op = out + (long long)blockIdx.z * zout;
    int x = blockIdx.x * 32 + threadIdx.x;
    int y0 = blockIdx.y * 32;
#pragma unroll
    for (int j = 0; j < 32; j += 8)
        t[threadIdx.y + j][threadIdx.x] = ip[(long long)(y0 + threadIdx.y + j) * Cc + x];
    __syncthreads();
    int xo = y0 + threadIdx.x;
    int yo0 = blockIdx.x * 32;
#pragma unroll
    for (int j = 0; j < 32; j += 8)
        op[(long long)(yo0 + threadIdx.y + j) * R + xo] = t[threadIdx.x][threadIdx.y + j];
}

// =====================================================================
// Row softmax in place. One block (256 threads) per row of 2048 floats.
// =====================================================================
__global__ void __launch_bounds__(256) softmax_rows_k(float* __restrict__ P)
{
    float4* r = reinterpret_cast<float4*>(P + (long long)blockIdx.x * S_);
    const int tid = threadIdx.x;

    float4 v0 = r[tid];
    float4 v1 = r[tid + 256];

    float mx = fmaxf(fmaxf(fmaxf(v0.x, v0.y), fmaxf(v0.z, v0.w)),
                     fmaxf(fmaxf(v1.x, v1.y), fmaxf(v1.z, v1.w)));
#pragma unroll
    for (int o = 16; o; o >>= 1) mx = fmaxf(mx, __shfl_xor_sync(0xffffffffu, mx, o));

    __shared__ float sred[8];
    if ((tid & 31) == 0) sred[tid >> 5] = mx;
    __syncthreads();
    float rowmax = sred[0];
#pragma unroll
    for (int w = 1; w < 8; w++) rowmax = fmaxf(rowmax, sred[w]);
    __syncthreads();

    v0.x = __expf(v0.x - rowmax); v0.y = __expf(v0.y - rowmax);
    v0.z = __expf(v0.z - rowmax); v0.w = __expf(v0.w - rowmax);
    v1.x = __expf(v1.x - rowmax); v1.y = __expf(v1.y - rowmax);
    v1.z = __expf(v1.z - rowmax); v1.w = __expf(v1.w - rowmax);

    float s = v0.x + v0.y + v0.z + v0.w + v1.x + v1.y + v1.z + v1.w;
#pragma unroll
    for (int o = 16; o; o >>= 1) s += __shfl_xor_sync(0xffffffffu, s, o);
    if ((tid & 31) == 0) sred[tid >> 5] = s;
    __syncthreads();
    float tot = 0.0f;
#pragma unroll
    for (int w = 0; w < 8; w++) tot += sred[w];
    float inv = __frcp_rn(tot);

    v0.x *= inv; v0.y *= inv; v0.z *= inv; v0.w *= inv;
    v1.x *= inv; v1.y *= inv; v1.z *= inv; v1.w *= inv;
    r[tid] = v0;
    r[tid + 256] = v1;
}

// =====================================================================
// Row LayerNorm
// =====================================================================
__global__ void __launch_bounds__(128)
layernorm_k(const float* __restrict__ in, const float* __restrict__ g,
            const float* __restrict__ b, float* __restrict__ out)
{
    const int tid = threadIdx.x;
    const float4* r = reinterpret_cast<const float4*>(in + (long long)blockIdx.x * D_);
    float4 v = r[tid];

    float s  = v.x + v.y + v.z + v.w;
    float sq = v.x * v.x + v.y * v.y + v.z * v.z + v.w * v.w;
#pragma unroll
    for (int o = 16; o; o >>= 1) {
        s  += __shfl_xor_sync(0xffffffffu, s, o);
        sq += __shfl_xor_sync(0xffffffffu, sq, o);
    }
    __shared__ float ssum[4], ssq[4];
    if ((tid & 31) == 0) { ssum[tid >> 5] = s; ssq[tid >> 5] = sq; }
    __syncthreads();
    s  = ssum[0] + ssum[1] + ssum[2] + ssum[3];
    sq = ssq[0] + ssq[1] + ssq[2] + ssq[3];

    const float mu  = s * (1.0f / D_);
    float var = sq * (1.0f / D_) - mu * mu;
    var = fmaxf(var, 0.0f);
    const float rstd = rsqrtf(var + 1e-5f);

    float4 gg = reinterpret_cast<const float4*>(g)[tid];
    float4 bb = reinterpret_cast<const float4*>(b)[tid];
    float4 o4;
    o4.x = (v.x - mu) * rstd * gg.x + bb.x;
    o4.y = (v.y - mu) * rstd * gg.y + bb.y;
    o4.z = (v.z - mu) * rstd * gg.z + bb.z;
    o4.w = (v.w - mu) * rstd * gg.w + bb.w;
    reinterpret_cast<float4*>(out + (long long)blockIdx.x * D_)[tid] = o4;
}

// =====================================================================
// Launcher
// =====================================================================
static constexpr int SMEM_BN64  = (2 * 128 * 36 + 2 * 64 * 36) * 4;   // 55296
static constexpr int SMEM_BN128 = (2 * 128 * 36 + 2 * 128 * 36) * 4;  // 73728

extern "C" void kernel_launch(void* const* d_in, const int* in_sizes, int n_in,
                              void* d_out, int out_size)
{
    (void)in_sizes; (void)n_in; (void)out_size;
    const float* x     = (const float*)d_in[0];
    const float* Wq    = (const float*)d_in[1];
    const float* bq    = (const float*)d_in[2];
    const float* Wk    = (const float*)d_in[3];
    const float* bk    = (const float*)d_in[4];
    const float* Wv    = (const float*)d_in[5];
    const float* bv    = (const float*)d_in[6];
    const float* Wo    = (const float*)d_in[7];
    const float* bo    = (const float*)d_in[8];
    const float* ln1_g = (const float*)d_in[9];
    const float* ln1_b = (const float*)d_in[10];
    const float* W1    = (const float*)d_in[11];
    const float* b1    = (const float*)d_in[12];
    const float* W2    = (const float*)d_in[13];
    const float* b2    = (const float*)d_in[14];
    const float* ln2_g = (const float*)d_in[15];
    const float* ln2_b = (const float*)d_in[16];
    float* out = (float*)d_out;

    float *q, *k, *v, *vT, *sc, *oc, *h1, *h, *ff, *h2;
    float *WqT, *WkT, *WvT, *WoT, *W1T, *W2T;
    cudaGetSymbolAddress((void**)&q,   g_q);
    cudaGetSymbolAddress((void**)&k,   g_k);
    cudaGetSymbolAddress((void**)&v,   g_v);
    cudaGetSymbolAddress((void**)&vT,  g_vT);
    cudaGetSymbolAddress((void**)&sc,  g_scores);
    cudaGetSymbolAddress((void**)&oc,  g_ocat);
    cudaGetSymbolAddress((void**)&h1,  g_h1);
    cudaGetSymbolAddress((void**)&h,   g_h);
    cudaGetSymbolAddress((void**)&ff,  g_ff);
    cudaGetSymbolAddress((void**)&h2,  g_h2);
    cudaGetSymbolAddress((void**)&WqT, g_WqT);
    cudaGetSymbolAddress((void**)&WkT, g_WkT);
    cudaGetSymbolAddress((void**)&WvT, g_WvT);
    cudaGetSymbolAddress((void**)&WoT, g_WoT);
    cudaGetSymbolAddress((void**)&W1T, g_W1T);
    cudaGetSymbolAddress((void**)&W2T, g_W2T);

    cudaFuncSetAttribute(mma_gemm<64, 0>,  cudaFuncAttributeMaxDynamicSharedMemorySize, SMEM_BN64);
    cudaFuncSetAttribute(mma_gemm<128, 0>, cudaFuncAttributeMaxDynamicSharedMemorySize, SMEM_BN128);
    cudaFuncSetAttribute(mma_gemm<128, 1>, cudaFuncAttributeMaxDynamicSharedMemorySize, SMEM_BN128);
    cudaFuncSetAttribute(mma_gemm<128, 2>, cudaFuncAttributeMaxDynamicSharedMemorySize, SMEM_BN128);

    const Off lin0      = {1, 0, 0};
    const Off oA_qkv    = {H_, (long long)S_ * D_, 0};
    const Off oB_qkv    = {H_, 0, (long long)DK_ * D_};
    const Off oBias_qkv = {H_, 0, (long long)DK_};
    const Off oC_qkv    = {1, (long long)S_ * DK_, 0};
    const Off oBH       = {1, (long long)S_ * DK_, 0};
    const Off oVT       = {1, (long long)DK_ * S_, 0};
    const Off oSC       = {1, (long long)S_ * S_, 0};
    const Off oCat      = {H_, (long long)S_ * D_, (long long)DK_};

    // ---- 0. transpose weights to [N,K] K-major layouts ----
    dim3 tb(32, 8);
    transpose_k<<<dim3(2, 16, H_), tb>>>(Wq, WqT, D_, DK_, (long long)D_ * DK_, (long long)DK_ * D_);
    transpose_k<<<dim3(2, 16, H_), tb>>>(Wk, WkT, D_, DK_, (long long)D_ * DK_, (long long)DK_ * D_);
    transpose_k<<<dim3(2, 16, H_), tb>>>(Wv, WvT, D_, DK_, (long long)D_ * DK_, (long long)DK_ * D_);
    transpose_k<<<dim3(16, 16, 1), tb>>>(Wo, WoT, D_, D_, 0, 0);
    transpose_k<<<dim3(64, 16, 1), tb>>>(W1, W1T, D_, DF_, 0, 0);
    transpose_k<<<dim3(16, 64, 1), tb>>>(W2, W2T, DF_, D_, 0, 0);

    // ---- 1-3. QKV projections: per (b,h) [2048,512] @ [64,512]^T ----
    mma_gemm<64, 0><<<dim3(1, 16, B_ * H_), 128, SMEM_BN64>>>(
        x, WqT, bq, nullptr, q, S_, DK_, D_, DK_, 1.0f, oA_qkv, oB_qkv, oBias_qkv, oC_qkv);
    mma_gemm<64, 0><<<dim3(1, 16, B_ * H_), 128, SMEM_BN64>>>(
        x, WkT, bk, nullptr, k, S_, DK_, D_, DK_, 1.0f, oA_qkv, oB_qkv, oBias_qkv, oC_qkv);
    mma_gemm<64, 0><<<dim3(1, 16, B_ * H_), 128, SMEM_BN64>>>(
        x, WvT, bv, nullptr, v, S_, DK_, D_, DK_, 1.0f, oA_qkv, oB_qkv, oBias_qkv, oC_qkv);

    // ---- 3b. vT[z] = v[z]^T ----
    transpose_k<<<dim3(2, 64, B_ * H_), tb>>>(v, vT, S_, DK_, (long long)S_ * DK_, (long long)DK_ * S_);

    // ---- 4. scores = (q @ k^T) / 8 ----
    mma_gemm<128, 0><<<dim3(16, 16, B_ * H_), 256, SMEM_BN128>>>(
        q, k, nullptr, nullptr, sc, S_, S_, DK_, S_, 0.125f, oBH, oBH, lin0, oSC);

    // ---- 5. softmax ----
    softmax_rows_k<<<B_ * H_ * S_, 256>>>(sc);

    // ---- 6. o = attn @ v (via vT), into concat layout ----
    mma_gemm<64, 0><<<dim3(1, 16, B_ * H_), 128, SMEM_BN64>>>(
        sc, vT, nullptr, nullptr, oc, S_, DK_, S_, D_, 1.0f, oSC, oVT, lin0, oCat);

    // ---- 7. h1 = x + ocat @ Wo + bo ----
    mma_gemm<128, 2><<<dim3(4, 32, 1), 256, SMEM_BN128>>>(
        oc, WoT, bo, x, h1, M_, D_, D_, D_, 1.0f, lin0, lin0, lin0, lin0);

    // ---- 8. h = LN1(h1) ----
    layernorm_k<<<M_, 128>>>(h1, ln1_g, ln1_b, h);

    // ---- 9. ff = relu(h @ W1 + b1) ----
    mma_gemm<128, 1><<<dim3(16, 32, 1), 256, SMEM_BN128>>>(
        h, W1T, b1, nullptr, ff, M_, DF_, D_, DF_, 1.0f, lin0, lin0, lin0, lin0);

    // ---- 10. h2 = h + ff @ W2 + b2 ----
    mma_gemm<128, 2><<<dim3(4, 32, 1), 256, SMEM_BN128>>>(
        ff, W2T, b2, h, h2, M_, D_, DF_, D_, 1.0f, lin0, lin0, lin0, lin0);

    // ---- 11. out = LN2(h2) ----
    layernorm_k<<<M_, 128>>>(h2, ln2_g, ln2_b, out);
}

// round 5
// speedup vs baseline: 3.3231x; 1.1656x over previous
#include <cuda_runtime.h>
#include <cstdint>
#include <math.h>

// Problem constants
static constexpr int B_  = 2;
static constexpr int S_  = 2048;
static constexpr int D_  = 512;
static constexpr int H_  = 8;
static constexpr int DK_ = 64;
static constexpr int DF_ = 2048;
static constexpr int M_  = B_ * S_;
static constexpr long long QKV_ELEMS = (long long)B_ * H_ * S_ * DK_;

// -------- scratch (device globals; no allocation allowed) --------
__device__ float g_q[QKV_ELEMS];
__device__ float g_k[QKV_ELEMS];
__device__ float g_v[QKV_ELEMS];
__device__ float g_vT[QKV_ELEMS];                 // [z][64][2048]
__device__ float g_ocat[(long long)M_ * D_];
__device__ float g_h1[(long long)M_ * D_];
__device__ float g_h [(long long)M_ * D_];
__device__ float g_ff[(long long)M_ * DF_];
__device__ float g_h2[(long long)M_ * D_];
__device__ float g_WqT[(long long)H_ * DK_ * D_]; // [h][64][512]
__device__ float g_WkT[(long long)H_ * DK_ * D_];
__device__ float g_WvT[(long long)H_ * DK_ * D_];
__device__ float g_WoT[(long long)D_ * D_];
__device__ float g_W1T[(long long)DF_ * D_];
__device__ float g_W2T[(long long)D_ * DF_];

// -------- batched offset descriptor --------
struct Off { int div; long long s1; long long s2; };
__device__ __forceinline__ long long offz(Off o, int z) {
    return (long long)(z / o.div) * o.s1 + (long long)(z % o.div) * o.s2;
}

// ===================== PTX helpers (baseline sm_80+ features only) =====================
__device__ __forceinline__ uint32_t smem_u32(const void* p) {
    uint32_t a;
    asm("{ .reg .u64 t; cvta.to.shared.u64 t, %1; cvt.u32.u64 %0, t; }" : "=r"(a) : "l"(p));
    return a;
}
__device__ __forceinline__ void cp16(uint32_t dst, const float* src) {
    asm volatile("cp.async.cg.shared.global [%0], [%1], 16;"
                 :: "r"(dst), "l"(__cvta_generic_to_global(src)) : "memory");
}
__device__ __forceinline__ uint32_t f2tf(float f) {
    uint32_t u;
    asm("cvt.rna.tf32.f32 %0, %1;" : "=r"(u) : "f"(f));
    return u;
}
__device__ __forceinline__ void mma8(float* d, const uint32_t* a, const uint32_t* b) {
    asm volatile(
        "mma.sync.aligned.m16n8k8.row.col.f32.tf32.tf32.f32 "
        "{%0,%1,%2,%3}, {%4,%5,%6,%7}, {%8,%9}, {%0,%1,%2,%3};"
        : "+f"(d[0]), "+f"(d[1]), "+f"(d[2]), "+f"(d[3])
        : "r"(a[0]), "r"(a[1]), "r"(a[2]), "r"(a[3]), "r"(b[0]), "r"(b[1]));
}

// =====================================================================
// tf32 mma.sync GEMM (unchanged, verified).  C[z] = alpha*A[z]@B[z]^T ...
// =====================================================================
template<int BN, int EPI>
__global__ void __launch_bounds__(2 * (BN / 32) * 32, 2)
mma_gemm(const float* __restrict__ A, const float* __restrict__ Bm,
         const float* __restrict__ bias, const float* __restrict__ res,
         float* __restrict__ C, int M, int N, int K, int ldc, float alpha,
         Off oA, Off oB, Off oBias, Off oC)
{
    constexpr int BM = 128;
    constexpr int BK = 32;
    constexpr int AW = 36;
    constexpr int NWN = BN / 32;
    constexpr int NT  = 2 * NWN * 32;
    constexpr int A_FLOATS = BM * AW;
    constexpr int B_FLOATS = BN * AW;
    constexpr int A_ITERS = (BM * 8) / NT;
    constexpr int B_ITERS = (BN * 8) / NT;

    extern __shared__ float smf[];
    float* sA = smf;
    float* sB = smf + 2 * A_FLOATS;
    const uint32_t uA = smem_u32(sA);
    const uint32_t uB = smem_u32(sB);

    const int tid  = threadIdx.x;
    const int wid  = tid >> 5;
    const int lane = tid & 31;
    const int gid  = lane >> 2;
    const int tig  = lane & 3;
    const int wn   = wid % NWN;
    const int wm   = wid / NWN;
    const int z    = blockIdx.z;

    A  += offz(oA, z);
    Bm += offz(oB, z);
    C  += offz(oC, z);
    const float* bptr = (bias != nullptr) ? bias + offz(oBias, z) : nullptr;

    const long long bm = (long long)blockIdx.y * BM;
    const long long bn = (long long)blockIdx.x * BN;
    const int T = K / BK;

    const float* aBase = A + bm * K;
    const float* bBase = Bm + bn * K;

    auto stage = [&](int t) {
        const int buf = t & 1;
        const float* aSrc = aBase + (long long)t * BK;
        const float* bSrc = bBase + (long long)t * BK;
        const uint32_t aDst = uA + (uint32_t)buf * A_FLOATS * 4;
        const uint32_t bDst = uB + (uint32_t)buf * B_FLOATS * 4;
#pragma unroll
        for (int i = 0; i < A_ITERS; i++) {
            int e = tid + i * NT;
            int r = e >> 3, c = e & 7;
            cp16(aDst + (uint32_t)(r * AW + c * 4) * 4, aSrc + (long long)r * K + c * 4);
        }
#pragma unroll
        for (int i = 0; i < B_ITERS; i++) {
            int e = tid + i * NT;
            int r = e >> 3, c = e & 7;
            cp16(bDst + (uint32_t)(r * AW + c * 4) * 4, bSrc + (long long)r * K + c * 4);
        }
        asm volatile("cp.async.commit_group;" ::: "memory");
    };

    float acc[4][4][4];
#pragma unroll
    for (int i = 0; i < 4; i++)
#pragma unroll
        for (int j = 0; j < 4; j++)
#pragma unroll
            for (int r = 0; r < 4; r++) acc[i][j][r] = 0.0f;

    stage(0);
    for (int t = 0; t < T; t++) {
        if (t + 1 < T) {
            stage(t + 1);
            asm volatile("cp.async.wait_group 1;" ::: "memory");
        } else {
            asm volatile("cp.async.wait_group 0;" ::: "memory");
        }
        __syncthreads();

        const float* As = sA + (t & 1) * A_FLOATS;
        const float* Bs = sB + (t & 1) * B_FLOATS;
#pragma unroll
        for (int ks = 0; ks < BK / 8; ks++) {
            const int kk = ks * 8 + tig;
            uint32_t af[4][4];
#pragma unroll
            for (int mi = 0; mi < 4; mi++) {
                const float* ap = As + (wm * 64 + mi * 16 + gid) * AW + kk;
                af[mi][0] = f2tf(ap[0]);
                af[mi][1] = f2tf(ap[8 * AW]);
                af[mi][2] = f2tf(ap[4]);
                af[mi][3] = f2tf(ap[8 * AW + 4]);
            }
            uint32_t bf[4][2];
#pragma unroll
            for (int nj = 0; nj < 4; nj++) {
                const float* bp = Bs + (wn * 32 + nj * 8 + gid) * AW + kk;
                bf[nj][0] = f2tf(bp[0]);
                bf[nj][1] = f2tf(bp[4]);
            }
#pragma unroll
            for (int mi = 0; mi < 4; mi++)
#pragma unroll
                for (int nj = 0; nj < 4; nj++)
                    mma8(acc[mi][nj], af[mi], bf[nj]);
        }
        __syncthreads();
    }

#pragma unroll
    for (int mi = 0; mi < 4; mi++) {
        const long long m0 = bm + wm * 64 + mi * 16 + gid;
#pragma unroll
        for (int nj = 0; nj < 4; nj++) {
            const long long n0 = bn + wn * 32 + nj * 8 + tig * 2;
            float2 bb = make_float2(0.0f, 0.0f);
            if (bptr) bb = *reinterpret_cast<const float2*>(bptr + n0);

            float2 o0, o1;
            o0.x = acc[mi][nj][0] * alpha + bb.x;
            o0.y = acc[mi][nj][1] * alpha + bb.y;
            o1.x = acc[mi][nj][2] * alpha + bb.x;
            o1.y = acc[mi][nj][3] * alpha + bb.y;
            if (EPI == 1) {
                o0.x = fmaxf(o0.x, 0.0f); o0.y = fmaxf(o0.y, 0.0f);
                o1.x = fmaxf(o1.x, 0.0f); o1.y = fmaxf(o1.y, 0.0f);
            }
            if (EPI == 2) {
                float2 r0 = *reinterpret_cast<const float2*>(res + m0 * ldc + n0);
                float2 r1 = *reinterpret_cast<const float2*>(res + (m0 + 8) * ldc + n0);
                o0.x += r0.x; o0.y += r0.y;
                o1.x += r1.x; o1.y += r1.y;
            }
            *reinterpret_cast<float2*>(C + m0 * ldc + n0) = o0;
            *reinterpret_cast<float2*>(C + (m0 + 8) * ldc + n0) = o1;
        }
    }
}

// =====================================================================
// Fused flash attention (tf32 mma).
//   For z = b*H+h: O[z] = softmax(Q[z] @ K[z]^T / 8) @ V[z]
//   Q,K: [2048,64] row-major.  VT: [64,2048] (dk-major, B-operand layout).
//   Output written into concat layout g_ocat[b*S + m][h*64 + dk].
// Block: 128 query rows, 8 warps (16 rows each). K/V tiles of 64 keys,
// cp.async double-buffered. Online softmax with quad shuffles.
// =====================================================================
__global__ void __launch_bounds__(256)
flash_attn(const float* __restrict__ Q, const float* __restrict__ K,
           const float* __restrict__ VT, float* __restrict__ Ocat)
{
    constexpr int PW = 68;                     // padded row stride (floats)
    constexpr int QP_FLOATS = 128 * PW;
    constexpr int KV_FLOATS = 64 * PW;
    constexpr int TKEYS = 64;
    constexpr int T = S_ / TKEYS;              // 32 key tiles

    extern __shared__ float sm[];
    float* sQP = sm;                           // Q staging, then P buffer
    float* sK  = sm + QP_FLOATS;               // [2][64][PW]
    float* sV  = sK + 2 * KV_FLOATS;           // [2][64][PW]
    const uint32_t uK = smem_u32(sK);
    const uint32_t uV = smem_u32(sV);

    const int tid  = threadIdx.x;
    const int wid  = tid >> 5;
    const int lane = tid & 31;
    const int gid  = lane >> 2;
    const int tig  = lane & 3;
    const int wr   = wid * 16;                 // warp's row base within tile

    const int z  = blockIdx.y;                 // b*H + h
    const int zb = z / H_;
    const int zh = z % H_;
    const long long m0 = (long long)blockIdx.x * 128;

    const float* Qz = Q  + (long long)z * S_ * DK_;
    const float* Kz = K  + (long long)z * S_ * DK_;
    const float* Vz = VT + (long long)z * DK_ * S_;

    // ---- stage Q tile [128][64] into sQP ----
#pragma unroll
    for (int i = 0; i < 8; i++) {
        int e = tid + i * 256;
        int r = e >> 4, c = e & 15;
        *reinterpret_cast<float4*>(&sQP[r * PW + c * 4]) =
            *reinterpret_cast<const float4*>(Qz + (m0 + r) * DK_ + c * 4);
    }
    __syncthreads();

    // ---- extract Q fragments (pre-scaled by 1/sqrt(dk) = 0.125) ----
    uint32_t qf[8][4];
#pragma unroll
    for (int ks = 0; ks < 8; ks++) {
        const float* qp = sQP + (wr + gid) * PW + ks * 8 + tig;
        qf[ks][0] = f2tf(0.125f * qp[0]);
        qf[ks][1] = f2tf(0.125f * qp[8 * PW]);
        qf[ks][2] = f2tf(0.125f * qp[4]);
        qf[ks][3] = f2tf(0.125f * qp[8 * PW + 4]);
    }
    __syncthreads();   // everyone done reading Q before sQP reused as P

    float oacc[8][4];
#pragma unroll
    for (int nj = 0; nj < 8; nj++)
#pragma unroll
        for (int r = 0; r < 4; r++) oacc[nj][r] = 0.0f;
    float mrow0 = -1e30f, mrow1 = -1e30f;
    float lrow0 = 0.0f,  lrow1 = 0.0f;

    auto stage = [&](int t) {
        const int buf = t & 1;
        const uint32_t kDst = uK + (uint32_t)buf * KV_FLOATS * 4;
        const uint32_t vDst = uV + (uint32_t)buf * KV_FLOATS * 4;
#pragma unroll
        for (int i = 0; i < 4; i++) {
            int e = tid + i * 256;
            int r = e >> 4, c = e & 15;
            cp16(kDst + (uint32_t)(r * PW + c * 4) * 4,
                 Kz + (long long)(t * TKEYS + r) * DK_ + c * 4);
        }
#pragma unroll
        for (int i = 0; i < 4; i++) {
            int e = tid + i * 256;
            int r = e >> 4, c = e & 15;
            cp16(vDst + (uint32_t)(r * PW + c * 4) * 4,
                 Vz + (long long)r * S_ + t * TKEYS + c * 4);
        }
        asm volatile("cp.async.commit_group;" ::: "memory");
    };

    stage(0);
    for (int t = 0; t < T; t++) {
        if (t + 1 < T) {
            stage(t + 1);
            asm volatile("cp.async.wait_group 1;" ::: "memory");
        } else {
            asm volatile("cp.async.wait_group 0;" ::: "memory");
        }
        __syncthreads();

        const float* Ks = sK + (t & 1) * KV_FLOATS;
        const float* Vs = sV + (t & 1) * KV_FLOATS;

        // ---- S = (Q/8) @ K^T for this key tile: 16 x 64 per warp ----
        float sacc[8][4];
#pragma unroll
        for (int nj = 0; nj < 8; nj++)
#pragma unroll
            for (int r = 0; r < 4; r++) sacc[nj][r] = 0.0f;
#pragma unroll
        for (int ks = 0; ks < 8; ks++) {
            const int kk = ks * 8 + tig;
#pragma unroll
            for (int nj = 0; nj < 8; nj++) {
                uint32_t bf[2];
                const float* bp = Ks + (nj * 8 + gid) * PW + kk;
                bf[0] = f2tf(bp[0]);
                bf[1] = f2tf(bp[4]);
                mma8(sacc[nj], qf[ks], bf);
            }
        }

        // ---- online softmax (rows wr+gid and wr+gid+8) ----
        float mx0 = -1e30f, mx1 = -1e30f;
#pragma unroll
        for (int nj = 0; nj < 8; nj++) {
            mx0 = fmaxf(mx0, fmaxf(sacc[nj][0], sacc[nj][1]));
            mx1 = fmaxf(mx1, fmaxf(sacc[nj][2], sacc[nj][3]));
        }
        mx0 = fmaxf(mx0, __shfl_xor_sync(0xffffffffu, mx0, 1));
        mx0 = fmaxf(mx0, __shfl_xor_sync(0xffffffffu, mx0, 2));
        mx1 = fmaxf(mx1, __shfl_xor_sync(0xffffffffu, mx1, 1));
        mx1 = fmaxf(mx1, __shfl_xor_sync(0xffffffffu, mx1, 2));

        const float mn0 = fmaxf(mrow0, mx0);
        const float mn1 = fmaxf(mrow1, mx1);
        const float sc0 = __expf(mrow0 - mn0);
        const float sc1 = __expf(mrow1 - mn1);
        mrow0 = mn0; mrow1 = mn1;

        float* p0row = sQP + (wr + gid) * PW;
        float* p1row = sQP + (wr + gid + 8) * PW;
        float ls0 = 0.0f, ls1 = 0.0f;
#pragma unroll
        for (int nj = 0; nj < 8; nj++) {
            float e0 = __expf(sacc[nj][0] - mn0);
            float e1 = __expf(sacc[nj][1] - mn0);
            float e2 = __expf(sacc[nj][2] - mn1);
            float e3 = __expf(sacc[nj][3] - mn1);
            ls0 += e0 + e1;
            ls1 += e2 + e3;
            *reinterpret_cast<float2*>(p0row + nj * 8 + tig * 2) = make_float2(e0, e1);
            *reinterpret_cast<float2*>(p1row + nj * 8 + tig * 2) = make_float2(e2, e3);
        }
        ls0 += __shfl_xor_sync(0xffffffffu, ls0, 1);
        ls0 += __shfl_xor_sync(0xffffffffu, ls0, 2);
        ls1 += __shfl_xor_sync(0xffffffffu, ls1, 1);
        ls1 += __shfl_xor_sync(0xffffffffu, ls1, 2);
        lrow0 = lrow0 * sc0 + ls0;
        lrow1 = lrow1 * sc1 + ls1;

#pragma unroll
        for (int nj = 0; nj < 8; nj++) {
            oacc[nj][0] *= sc0; oacc[nj][1] *= sc0;
            oacc[nj][2] *= sc1; oacc[nj][3] *= sc1;
        }
        __syncwarp();

        // ---- O += P @ V  (P in sQP warp-private rows, V from sV) ----
#pragma unroll
        for (int ks = 0; ks < 8; ks++) {
            const int kk = ks * 8 + tig;
            uint32_t pf[4];
            const float* pp = sQP + (wr + gid) * PW + kk;
            pf[0] = f2tf(pp[0]);
            pf[1] = f2tf(pp[8 * PW]);
            pf[2] = f2tf(pp[4]);
            pf[3] = f2tf(pp[8 * PW + 4]);
#pragma unroll
            for (int nj = 0; nj < 8; nj++) {
                uint32_t vf[2];
                const float* vp = Vs + (nj * 8 + gid) * PW + kk;
                vf[0] = f2tf(vp[0]);
                vf[1] = f2tf(vp[4]);
                mma8(oacc[nj], pf, vf);
            }
        }
        __syncthreads();   // all reads of this K/V buffer done before restage
    }

    // ---- epilogue: normalize and write into concat layout ----
    const float inv0 = 1.0f / lrow0;
    const float inv1 = 1.0f / lrow1;
    const long long row0 = (long long)zb * S_ + m0 + wr + gid;
    const long long row1 = row0 + 8;
    float* o0 = Ocat + row0 * D_ + zh * DK_;
    float* o1 = Ocat + row1 * D_ + zh * DK_;
#pragma unroll
    for (int nj = 0; nj < 8; nj++) {
        const int c = nj * 8 + tig * 2;
        *reinterpret_cast<float2*>(o0 + c) =
            make_float2(oacc[nj][0] * inv0, oacc[nj][1] * inv0);
        *reinterpret_cast<float2*>(o1 + c) =
            make_float2(oacc[nj][2] * inv1, oacc[nj][3] * inv1);
    }
}

// =====================================================================
// 32x32 tiled transpose: out[z][c][r] = in[z][r][c]
// =====================================================================
__global__ void __launch_bounds__(256)
transpose_k(const float* __restrict__ in, float* __restrict__ out,
            int R, int Cc, long long zin, long long zout)
{
    __shared__ float t[32][33];
    const float* ip = in + (long long)blockIdx.z * zin;
    float* op = out + (long long)blockIdx.z * zout;
    int x = blockIdx.x * 32 + threadIdx.x;
    int y0 = blockIdx.y * 32;
#pragma unroll
    for (int j = 0; j < 32; j += 8)
        t[threadIdx.y + j][threadIdx.x] = ip[(long long)(y0 + threadIdx.y + j) * Cc + x];
    __syncthreads();
    int xo = y0 + threadIdx.x;
    int yo0 = blockIdx.x * 32;
#pragma unroll
    for (int j = 0; j < 32; j += 8)
        op[(long long)(yo0 + threadIdx.y + j) * R + xo] = t[threadIdx.x][threadIdx.y + j];
}

// =====================================================================
// Row LayerNorm
// =====================================================================
__global__ void __launch_bounds__(128)
layernorm_k(const float* __restrict__ in, const float* __restrict__ g,
            const float* __restrict__ b, float* __restrict__ out)
{
    const int tid = threadIdx.x;
    const float4* r = reinterpret_cast<const float4*>(in + (long long)blockIdx.x * D_);
    float4 v = r[tid];

    float s  = v.x + v.y + v.z + v.w;
    float sq = v.x * v.x + v.y * v.y + v.z * v.z + v.w * v.w;
#pragma unroll
    for (int o = 16; o; o >>= 1) {
        s  += __shfl_xor_sync(0xffffffffu, s, o);
        sq += __shfl_xor_sync(0xffffffffu, sq, o);
    }
    __shared__ float ssum[4], ssq[4];
    if ((tid & 31) == 0) { ssum[tid >> 5] = s; ssq[tid >> 5] = sq; }
    __syncthreads();
    s  = ssum[0] + ssum[1] + ssum[2] + ssum[3];
    sq = ssq[0] + ssq[1] + ssq[2] + ssq[3];

    const float mu  = s * (1.0f / D_);
    float var = sq * (1.0f / D_) - mu * mu;
    var = fmaxf(var, 0.0f);
    const float rstd = rsqrtf(var + 1e-5f);

    float4 gg = reinterpret_cast<const float4*>(g)[tid];
    float4 bb = reinterpret_cast<const float4*>(b)[tid];
    float4 o4;
    o4.x = (v.x - mu) * rstd * gg.x + bb.x;
    o4.y = (v.y - mu) * rstd * gg.y + bb.y;
    o4.z = (v.z - mu) * rstd * gg.z + bb.z;
    o4.w = (v.w - mu) * rstd * gg.w + bb.w;
    reinterpret_cast<float4*>(out + (long long)blockIdx.x * D_)[tid] = o4;
}

// =====================================================================
// Launcher
// =====================================================================
static constexpr int SMEM_BN64  = (2 * 128 * 36 + 2 * 64 * 36) * 4;   // 55296
static constexpr int SMEM_BN128 = (2 * 128 * 36 + 2 * 128 * 36) * 4;  // 73728
static constexpr int SMEM_FLASH = (128 * 68 + 4 * 64 * 68) * 4;       // 104448

extern "C" void kernel_launch(void* const* d_in, const int* in_sizes, int n_in,
                              void* d_out, int out_size)
{
    (void)in_sizes; (void)n_in; (void)out_size;
    const float* x     = (const float*)d_in[0];
    const float* Wq    = (const float*)d_in[1];
    const float* bq    = (const float*)d_in[2];
    const float* Wk    = (const float*)d_in[3];
    const float* bk    = (const float*)d_in[4];
    const float* Wv    = (const float*)d_in[5];
    const float* bv    = (const float*)d_in[6];
    const float* Wo    = (const float*)d_in[7];
    const float* bo    = (const float*)d_in[8];
    const float* ln1_g = (const float*)d_in[9];
    const float* ln1_b = (const float*)d_in[10];
    const float* W1    = (const float*)d_in[11];
    const float* b1    = (const float*)d_in[12];
    const float* W2    = (const float*)d_in[13];
    const float* b2    = (const float*)d_in[14];
    const float* ln2_g = (const float*)d_in[15];
    const float* ln2_b = (const float*)d_in[16];
    float* out = (float*)d_out;

    float *q, *k, *v, *vT, *oc, *h1, *h, *ff, *h2;
    float *WqT, *WkT, *WvT, *WoT, *W1T, *W2T;
    cudaGetSymbolAddress((void**)&q,   g_q);
    cudaGetSymbolAddress((void**)&k,   g_k);
    cudaGetSymbolAddress((void**)&v,   g_v);
    cudaGetSymbolAddress((void**)&vT,  g_vT);
    cudaGetSymbolAddress((void**)&oc,  g_ocat);
    cudaGetSymbolAddress((void**)&h1,  g_h1);
    cudaGetSymbolAddress((void**)&h,   g_h);
    cudaGetSymbolAddress((void**)&ff,  g_ff);
    cudaGetSymbolAddress((void**)&h2,  g_h2);
    cudaGetSymbolAddress((void**)&WqT, g_WqT);
    cudaGetSymbolAddress((void**)&WkT, g_WkT);
    cudaGetSymbolAddress((void**)&WvT, g_WvT);
    cudaGetSymbolAddress((void**)&WoT, g_WoT);
    cudaGetSymbolAddress((void**)&W1T, g_W1T);
    cudaGetSymbolAddress((void**)&W2T, g_W2T);

    cudaFuncSetAttribute(mma_gemm<64, 0>,  cudaFuncAttributeMaxDynamicSharedMemorySize, SMEM_BN64);
    cudaFuncSetAttribute(mma_gemm<128, 0>, cudaFuncAttributeMaxDynamicSharedMemorySize, SMEM_BN128);
    cudaFuncSetAttribute(mma_gemm<128, 1>, cudaFuncAttributeMaxDynamicSharedMemorySize, SMEM_BN128);
    cudaFuncSetAttribute(mma_gemm<128, 2>, cudaFuncAttributeMaxDynamicSharedMemorySize, SMEM_BN128);
    cudaFuncSetAttribute(flash_attn,       cudaFuncAttributeMaxDynamicSharedMemorySize, SMEM_FLASH);

    const Off lin0      = {1, 0, 0};
    const Off oA_qkv    = {H_, (long long)S_ * D_, 0};
    const Off oB_qkv    = {H_, 0, (long long)DK_ * D_};
    const Off oBias_qkv = {H_, 0, (long long)DK_};
    const Off oC_qkv    = {1, (long long)S_ * DK_, 0};

    // ---- 0. transpose weights to [N,K] K-major layouts ----
    dim3 tb(32, 8);
    transpose_k<<<dim3(2, 16, H_), tb>>>(Wq, WqT, D_, DK_, (long long)D_ * DK_, (long long)DK_ * D_);
    transpose_k<<<dim3(2, 16, H_), tb>>>(Wk, WkT, D_, DK_, (long long)D_ * DK_, (long long)DK_ * D_);
    transpose_k<<<dim3(2, 16, H_), tb>>>(Wv, WvT, D_, DK_, (long long)D_ * DK_, (long long)DK_ * D_);
    transpose_k<<<dim3(16, 16, 1), tb>>>(Wo, WoT, D_, D_, 0, 0);
    transpose_k<<<dim3(64, 16, 1), tb>>>(W1, W1T, D_, DF_, 0, 0);
    transpose_k<<<dim3(16, 64, 1), tb>>>(W2, W2T, DF_, D_, 0, 0);

    // ---- 1-3. QKV projections ----
    mma_gemm<64, 0><<<dim3(1, 16, B_ * H_), 128, SMEM_BN64>>>(
        x, WqT, bq, nullptr, q, S_, DK_, D_, DK_, 1.0f, oA_qkv, oB_qkv, oBias_qkv, oC_qkv);
    mma_gemm<64, 0><<<dim3(1, 16, B_ * H_), 128, SMEM_BN64>>>(
        x, WkT, bk, nullptr, k, S_, DK_, D_, DK_, 1.0f, oA_qkv, oB_qkv, oBias_qkv, oC_qkv);
    mma_gemm<64, 0><<<dim3(1, 16, B_ * H_), 128, SMEM_BN64>>>(
        x, WvT, bv, nullptr, v, S_, DK_, D_, DK_, 1.0f, oA_qkv, oB_qkv, oBias_qkv, oC_qkv);

    // ---- 3b. vT[z] = v[z]^T ----
    transpose_k<<<dim3(2, 64, B_ * H_), tb>>>(v, vT, S_, DK_, (long long)S_ * DK_, (long long)DK_ * S_);

    // ---- 4. fused flash attention -> concat layout ----
    flash_attn<<<dim3(S_ / 128, B_ * H_), 256, SMEM_FLASH>>>(q, k, vT, oc);

    // ---- 5. h1 = x + ocat @ Wo + bo ----
    mma_gemm<128, 2><<<dim3(4, 32, 1), 256, SMEM_BN128>>>(
        oc, WoT, bo, x, h1, M_, D_, D_, D_, 1.0f, lin0, lin0, lin0, lin0);

    // ---- 6. h = LN1(h1) ----
    layernorm_k<<<M_, 128>>>(h1, ln1_g, ln1_b, h);

    // ---- 7. ff = relu(h @ W1 + b1) ----
    mma_gemm<128, 1><<<dim3(16, 32, 1), 256, SMEM_BN128>>>(
        h, W1T, b1, nullptr, ff, M_, DF_, D_, DF_, 1.0f, lin0, lin0, lin0, lin0);

    // ---- 8. h2 = h + ff @ W2 + b2 ----
    mma_gemm<128, 2><<<dim3(4, 32, 1), 256, SMEM_BN128>>>(
        ff, W2T, b2, h, h2, M_, D_, DF_, D_, 1.0f, lin0, lin0, lin0, lin0);

    // ---- 9. out = LN2(h2) ----
    layernorm_k<<<M_, 128>>>(h2, ln2_g, ln2_b, out);
}